// round 1
// baseline (speedup 1.0000x reference)
#include <cuda_runtime.h>
#include <math.h>

#define B_      16
#define C_IN    512
#define C_OUT   512
#define KSZ     3
#define H_      64
#define W_      64
#define STYLE_D 512

// 1/sqrt(512), 1/sqrt(512*9)
#define MOD_SCALE  0.04419417382415922f
#define CONV_SCALE 0.014731391274719738f
#define EPS_       1e-8f

// Scratch (allocation-free rule: __device__ globals)
__device__ float g_s[B_ * C_IN];        // modulation  s[b][ci]
__device__ float g_wsq[C_OUT * C_IN];   // sum_k W^2 [co][ci]
__device__ float g_demod[B_ * C_OUT];   // demod scale [b][co]

// ---------------------------------------------------------------------------
// K0: s[b,ci] = sum_d style[b,d]*mod_weight[ci,d]*MOD_SCALE + bias[ci]
// grid = B_, block = 512 (one thread per ci)
// ---------------------------------------------------------------------------
__global__ void style_kernel(const float* __restrict__ style,
                             const float* __restrict__ modw,
                             const float* __restrict__ modb) {
    int b  = blockIdx.x;
    int ci = threadIdx.x;
    __shared__ float st[STYLE_D];
    st[ci] = style[b * STYLE_D + ci];
    __syncthreads();
    const float* wrow = modw + (size_t)ci * STYLE_D;
    float acc = 0.f;
#pragma unroll 8
    for (int d = 0; d < STYLE_D; d++) acc += st[d] * wrow[d];
    g_s[b * C_IN + ci] = acc * MOD_SCALE + modb[ci];
}

// ---------------------------------------------------------------------------
// K1: wsq[co,ci] = sum_k W[co,ci,k]^2
// ---------------------------------------------------------------------------
__global__ void wsq_kernel(const float* __restrict__ w) {
    int i = blockIdx.x * blockDim.x + threadIdx.x;
    if (i < C_OUT * C_IN) {
        const float* p = w + (size_t)i * 9;
        float a = 0.f;
#pragma unroll
        for (int k = 0; k < 9; k++) a += p[k] * p[k];
        g_wsq[i] = a;
    }
}

// ---------------------------------------------------------------------------
// K2: demod[b,co] = rsqrt(CONV_SCALE^2 * sum_ci s^2[b,ci]*wsq[co,ci] + eps)
// grid = B_, block = 512 (one thread per co)
// ---------------------------------------------------------------------------
__global__ void demod_kernel() {
    int b  = blockIdx.x;
    int co = threadIdx.x;
    __shared__ float s2[C_IN];
    float sv = g_s[b * C_IN + co];
    s2[co] = sv * sv;
    __syncthreads();
    const float* q = g_wsq + (size_t)co * C_IN;
    float a = 0.f;
#pragma unroll 8
    for (int ci = 0; ci < C_IN; ci++) a += s2[ci] * q[ci];
    g_demod[b * C_OUT + co] = rsqrtf(a * (CONV_SCALE * CONV_SCALE) + EPS_);
}

// ---------------------------------------------------------------------------
// K3: conv. out[b,co,y,x] = demod[b,co]*CONV_SCALE *
//          sum_{ci,kh,kw} (input[b,ci,y+kh-1,x+kw-1]*s[b,ci]) * W[co,ci,kh,kw]
//
// Tiling: block = (co tile 32) x (4 rows x 64 cols). 256 threads.
// Each thread: 4 co x 8 px accumulators. ci processed in chunks of 8.
// ---------------------------------------------------------------------------
#define CI_CHUNK 8
#define CO_TILE  32
#define H_TILE   4
#define W_SM     66   // 64 + 2 halo

__global__ __launch_bounds__(256, 2)
void conv_kernel(const float* __restrict__ input,
                 const float* __restrict__ W,
                 float* __restrict__ out) {
    const int cot = blockIdx.x;   // 0..15
    const int ht  = blockIdx.y;   // 0..15
    const int b   = blockIdx.z;   // 0..15
    const int y0  = ht * H_TILE;
    const int co0 = cot * CO_TILE;

    __shared__ float sIn[CI_CHUNK][H_TILE + 2][W_SM];
    __shared__ float sW[CI_CHUNK][CO_TILE][9];
    __shared__ float sS[C_IN];

    const int tid = threadIdx.x;
    sS[tid]       = g_s[b * C_IN + tid];
    sS[tid + 256] = g_s[b * C_IN + tid + 256];
    __syncthreads();

    const int g  = tid & 31;        // pixel group 0..31
    const int cg = tid >> 5;        // co group 0..7 (4 channels each)
    const int r  = g >> 3;          // row in tile 0..3
    const int xb = (g & 7) * 8;     // x base (8 consecutive px)

    float acc[4][8];
#pragma unroll
    for (int c = 0; c < 4; c++)
#pragma unroll
        for (int p = 0; p < 8; p++) acc[c][p] = 0.f;

    const float* inB = input + (size_t)b * C_IN * H_ * W_;

    for (int c0 = 0; c0 < C_IN; c0 += CI_CHUNK) {
        // ---- load input tile (with halo), pre-modulated by s[b,ci] ----
        for (int idx = tid; idx < CI_CHUNK * (H_TILE + 2) * W_SM; idx += 256) {
            int ci  = idx / ((H_TILE + 2) * W_SM);
            int rem = idx % ((H_TILE + 2) * W_SM);
            int row = rem / W_SM;
            int col = rem % W_SM;
            int y = y0 + row - 1;
            int x = col - 1;
            float v = 0.f;
            if ((unsigned)y < H_ && (unsigned)x < W_)
                v = inB[((size_t)(c0 + ci) * H_ + y) * W_ + x] * sS[c0 + ci];
            (&sIn[0][0][0])[idx] = v;
        }
        // ---- load weight tile ----
        for (int idx = tid; idx < CI_CHUNK * CO_TILE * 9; idx += 256) {
            int ci  = idx / (CO_TILE * 9);
            int rem = idx % (CO_TILE * 9);
            int co  = rem / 9;
            int k   = rem % 9;
            sW[ci][co][k] = W[((size_t)(co0 + co) * C_IN + (c0 + ci)) * 9 + k];
        }
        __syncthreads();

        // ---- compute ----
#pragma unroll
        for (int ci = 0; ci < CI_CHUNK; ci++) {
#pragma unroll
            for (int kh = 0; kh < 3; kh++) {
                float xr[10];
#pragma unroll
                for (int j = 0; j < 10; j++) xr[j] = sIn[ci][r + kh][xb + j];
#pragma unroll
                for (int kw = 0; kw < 3; kw++) {
                    const float w0 = sW[ci][cg * 4 + 0][kh * 3 + kw];
                    const float w1 = sW[ci][cg * 4 + 1][kh * 3 + kw];
                    const float w2 = sW[ci][cg * 4 + 2][kh * 3 + kw];
                    const float w3 = sW[ci][cg * 4 + 3][kh * 3 + kw];
#pragma unroll
                    for (int px = 0; px < 8; px++) {
                        const float xv = xr[px + kw];
                        acc[0][px] += xv * w0;
                        acc[1][px] += xv * w1;
                        acc[2][px] += xv * w2;
                        acc[3][px] += xv * w3;
                    }
                }
            }
        }
        __syncthreads();
    }

    // ---- epilogue: scale by demod * CONV_SCALE, store ----
    const int y = y0 + r;
#pragma unroll
    for (int c = 0; c < 4; c++) {
        const int cog = co0 + cg * 4 + c;
        const float sc = g_demod[b * C_OUT + cog] * CONV_SCALE;
        float* op = out + (((size_t)b * C_OUT + cog) * H_ + y) * W_ + xb;
        float4 v0, v1;
        v0.x = acc[c][0] * sc; v0.y = acc[c][1] * sc;
        v0.z = acc[c][2] * sc; v0.w = acc[c][3] * sc;
        v1.x = acc[c][4] * sc; v1.y = acc[c][5] * sc;
        v1.z = acc[c][6] * sc; v1.w = acc[c][7] * sc;
        *(float4*)(op)     = v0;
        *(float4*)(op + 4) = v1;
    }
}

// ---------------------------------------------------------------------------
extern "C" void kernel_launch(void* const* d_in, const int* in_sizes, int n_in,
                              void* d_out, int out_size) {
    const float* input = (const float*)d_in[0];
    const float* style = (const float*)d_in[1];
    const float* convw = (const float*)d_in[2];
    const float* modw  = (const float*)d_in[3];
    const float* modb  = (const float*)d_in[4];
    float* out = (float*)d_out;

    style_kernel<<<B_, STYLE_D>>>(style, modw, modb);
    wsq_kernel<<<(C_OUT * C_IN + 511) / 512, 512>>>(convw);
    demod_kernel<<<B_, C_OUT>>>();
    conv_kernel<<<dim3(C_OUT / CO_TILE, H_ / H_TILE, B_), 256>>>(input, convw, out);
}

// round 5
// speedup vs baseline: 2.9440x; 2.9440x over previous
#include <cuda_runtime.h>
#include <cstdint>
#include <math.h>

#define B_      16
#define C_IN    512
#define C_OUT   512
#define HW_     4096
#define K_TOT   4608
#define STYLE_D 512

#define MOD_SCALE  0.04419417382415922f
#define CONV_SCALE 0.014731391274719738f
#define EPS_       1e-8f

// ---------------- device scratch (allocation-free rule) ----------------
__device__ float g_s[B_ * C_IN];
__device__ float g_wsq[C_OUT * C_IN];
__device__ float g_demod[B_ * C_OUT];
__device__ float g_A[(size_t)C_OUT * K_TOT];            // 9.4 MB, tf32-rounded
__device__ float g_X[(size_t)B_ * HW_ * K_TOT];         // 1.21 GB im2col, tf32-rounded

// ---------------- helpers ----------------
__device__ __forceinline__ float to_tf32(float v) {
    asm("cvt.rna.tf32.f32 %0, %0;" : "+f"(v));
    return v;
}
__device__ __forceinline__ uint32_t s2u(const void* p) {
    uint32_t a;
    asm("{ .reg .u64 t; cvta.to.shared.u64 t, %1; cvt.u32.u64 %0, t; }" : "=r"(a) : "l"(p));
    return a;
}
__device__ __forceinline__ void cp16(uint32_t dst, const void* src) {
    asm volatile("cp.async.cg.shared.global [%0], [%1], 16;" :: "r"(dst), "l"(src));
}
__device__ __forceinline__ void cp_commit() {
    asm volatile("cp.async.commit_group;");
}
template <int N>
__device__ __forceinline__ void cp_wait() {
    asm volatile("cp.async.wait_group %0;" :: "n"(N));
}

// mma.sync m16n8k8 tf32 (sm_80+, valid on plain compute_103 target)
__device__ __forceinline__ void mma8(float* d, const uint32_t* a, const uint32_t* b) {
    asm volatile(
        "mma.sync.aligned.m16n8k8.row.col.f32.tf32.tf32.f32 "
        "{%0,%1,%2,%3}, {%4,%5,%6,%7}, {%8,%9}, {%0,%1,%2,%3};"
        : "+f"(d[0]), "+f"(d[1]), "+f"(d[2]), "+f"(d[3])
        : "r"(a[0]), "r"(a[1]), "r"(a[2]), "r"(a[3]), "r"(b[0]), "r"(b[1]));
}

// ---------------------------------------------------------------------------
// K0: s[b,ci] = style @ (modw*MOD_SCALE)^T + bias
// ---------------------------------------------------------------------------
__global__ void style_kernel(const float* __restrict__ style,
                             const float* __restrict__ modw,
                             const float* __restrict__ modb) {
    int b = blockIdx.x, ci = threadIdx.x;
    __shared__ float st[STYLE_D];
    st[ci] = style[b * STYLE_D + ci];
    __syncthreads();
    const float* wr = modw + (size_t)ci * STYLE_D;
    float acc = 0.f;
#pragma unroll 8
    for (int d = 0; d < STYLE_D; d++) acc += st[d] * wr[d];
    g_s[b * C_IN + ci] = acc * MOD_SCALE + modb[ci];
}

// ---------------------------------------------------------------------------
// K1: wsq[co,ci] = sum_k W^2
// ---------------------------------------------------------------------------
__global__ void wsq_kernel(const float* __restrict__ w) {
    int i = blockIdx.x * blockDim.x + threadIdx.x;
    if (i < C_OUT * C_IN) {
        const float* p = w + (size_t)i * 9;
        float a = 0.f;
#pragma unroll
        for (int k = 0; k < 9; k++) a += p[k] * p[k];
        g_wsq[i] = a;
    }
}

// ---------------------------------------------------------------------------
// K2: demod[b,co] = rsqrt(CONV_SCALE^2 * sum_ci s^2*wsq + eps)
// ---------------------------------------------------------------------------
__global__ void demod_kernel() {
    int b = blockIdx.x, co = threadIdx.x;
    __shared__ float s2[C_IN];
    float sv = g_s[b * C_IN + co];
    s2[co] = sv * sv;
    __syncthreads();
    const float* q = g_wsq + (size_t)co * C_IN;
    float a = 0.f;
#pragma unroll 8
    for (int ci = 0; ci < C_IN; ci++) a += s2[ci] * q[ci];
    g_demod[b * C_OUT + co] = rsqrtf(a * (CONV_SCALE * CONV_SCALE) + EPS_);
}

// ---------------------------------------------------------------------------
// K3: A[co][K], K = k*512+ci, tf32-rounded
// ---------------------------------------------------------------------------
__global__ void apack_kernel(const float* __restrict__ w) {
    int co = blockIdx.y;
    int Kp = blockIdx.x * 256 + threadIdx.x;
    int k = Kp >> 9, ci = Kp & 511;
    g_A[(size_t)co * K_TOT + Kp] = to_tf32(w[((size_t)co * 512 + ci) * 9 + k]);
}

// ---------------------------------------------------------------------------
// K4: im2col. g_X[b][y*64+x][k*512+ci] = tf32(input[b,ci,y+kh-1,x+kw-1]*s[b,ci])
// ---------------------------------------------------------------------------
__global__ __launch_bounds__(256) void im2col_kernel(const float* __restrict__ input) {
    const int ci0 = blockIdx.x * 32;
    const int y   = blockIdx.y;
    const int b   = blockIdx.z;
    const int t   = threadIdx.x;
    __shared__ float In3[32][3][68];
    __shared__ float sS[32];
    if (t < 32) sS[t] = g_s[b * C_IN + ci0 + t];
    __syncthreads();
    for (int idx = t; idx < 32 * 3 * 66; idx += 256) {
        int ci = idx / 198, r = idx % 198, dy = r / 66, xx = r % 66;
        int ys = y + dy - 1, xs = xx - 1;
        float v = 0.f;
        if ((unsigned)ys < 64 && (unsigned)xs < 64)
            v = input[(((size_t)b * C_IN + ci0 + ci) * 64 + ys) * 64 + xs] * sS[ci];
        In3[ci][dy][xx] = to_tf32(v);
    }
    __syncthreads();
    const size_t rowbase = (size_t)b * HW_ + y * 64;
#pragma unroll
    for (int k = 0; k < 9; k++) {
        const int kh = k / 3, kw = k % 3;
#pragma unroll
        for (int rep = 0; rep < 8; rep++) {
            int idx = rep * 256 + t;
            int x = idx >> 5, i = idx & 31;
            g_X[(rowbase + x) * K_TOT + k * 512 + ci0 + i] = In3[i][kh][x + kw];
        }
    }
}

// ---------------------------------------------------------------------------
// K5: GEMM via mma.sync tf32. CTA: M=128 co x N=128 px, K=4608, 144 stages of 32.
// 8 warps (2 M x 4 N), warp tile 64x32. 4-stage cp.async ring.
// smem tile layout: [row][36 floats] (32 K + 4 pad) -> conflict-free frag loads.
// ---------------------------------------------------------------------------
#define RS        36          // row stride in floats (144 B)
#define TILE_B    (128 * RS * 4)       // 18432 B per operand tile
#define STAGE_B   (2 * TILE_B)         // 36864 B
#define NSTAGE    4
#define NS        144
#define DYN_SMEM  (NSTAGE * STAGE_B)   // 147456 B

__global__ __launch_bounds__(256, 1) void gemm_kernel(float* __restrict__ out) {
    extern __shared__ float smem[];
    const uint32_t sb = s2u(smem);
    const int t = threadIdx.x;
    const int w = t >> 5, lane = t & 31;
    const int mw = w >> 2;        // 0..1  (M warp row)
    const int nw = w & 3;         // 0..3  (N warp col)

    const int co0 = blockIdx.x * 128;   // co fastest -> X-tile sharing CTAs adjacent
    const int p0  = blockIdx.y * 128;
    const int b   = blockIdx.z;

    const float* Ab = g_A + (size_t)co0 * K_TOT;
    const float* Xb = g_X + ((size_t)b * HW_ + p0) * K_TOT;

    // ---- async stage loader: 2048 x 16B chunks, 8 per thread ----
    auto load_stage = [&](int stage) {
        const uint32_t base = sb + (stage & (NSTAGE - 1)) * STAGE_B;
        const int koff = stage * 32;
#pragma unroll
        for (int j = 0; j < 4; j++) {
            int idx = j * 256 + t;          // 0..1023
            int row = idx >> 3, ch = (idx & 7) * 4;
            cp16(base + (row * RS + ch) * 4, Ab + (size_t)row * K_TOT + koff + ch);
        }
#pragma unroll
        for (int j = 0; j < 4; j++) {
            int idx = j * 256 + t;
            int row = idx >> 3, ch = (idx & 7) * 4;
            cp16(base + TILE_B + (row * RS + ch) * 4, Xb + (size_t)row * K_TOT + koff + ch);
        }
        cp_commit();
    };

    float acc[4][4][4];
#pragma unroll
    for (int i = 0; i < 4; i++)
#pragma unroll
        for (int j = 0; j < 4; j++)
#pragma unroll
            for (int c = 0; c < 4; c++) acc[i][j][c] = 0.f;

    load_stage(0);
    load_stage(1);
    load_stage(2);

    const int lr = lane >> 2;   // 0..7
    const int lc = lane & 3;    // 0..3

    for (int i = 0; i < NS; i++) {
        cp_wait<2>();
        __syncthreads();
        if (i + 3 < NS) load_stage(i + 3);

        const float* As = smem + (i & (NSTAGE - 1)) * (STAGE_B / 4);
        const float* Bs = As + (TILE_B / 4);

#pragma unroll
        for (int ks = 0; ks < 4; ks++) {
            const int kc = ks * 8 + lc;
            uint32_t af[4][4], bf[4][2];
#pragma unroll
            for (int mf = 0; mf < 4; mf++) {
                const int r0 = mw * 64 + mf * 16 + lr;
                af[mf][0] = __float_as_uint(As[r0 * RS + kc]);
                af[mf][1] = __float_as_uint(As[(r0 + 8) * RS + kc]);
                af[mf][2] = __float_as_uint(As[r0 * RS + kc + 4]);
                af[mf][3] = __float_as_uint(As[(r0 + 8) * RS + kc + 4]);
            }
#pragma unroll
            for (int nf = 0; nf < 4; nf++) {
                const int pr = nw * 32 + nf * 8 + lr;
                bf[nf][0] = __float_as_uint(Bs[pr * RS + kc]);
                bf[nf][1] = __float_as_uint(Bs[pr * RS + kc + 4]);
            }
#pragma unroll
            for (int mf = 0; mf < 4; mf++)
#pragma unroll
                for (int nf = 0; nf < 4; nf++)
                    mma8(acc[mf][nf], af[mf], bf[nf]);
        }
        __syncthreads();
    }

    // ---- epilogue: scale by demod*CONV_SCALE, write float2 ----
#pragma unroll
    for (int mf = 0; mf < 4; mf++) {
        const int coA = co0 + mw * 64 + mf * 16 + lr;
        const int coB = coA + 8;
        const float scA = g_demod[b * C_OUT + coA] * CONV_SCALE;
        const float scB = g_demod[b * C_OUT + coB] * CONV_SCALE;
        float* opA = out + ((size_t)b * C_OUT + coA) * HW_ + p0;
        float* opB = out + ((size_t)b * C_OUT + coB) * HW_ + p0;
#pragma unroll
        for (int nf = 0; nf < 4; nf++) {
            const int px = nw * 32 + nf * 8 + lc * 2;
            float2 vA, vB;
            vA.x = acc[mf][nf][0] * scA; vA.y = acc[mf][nf][1] * scA;
            vB.x = acc[mf][nf][2] * scB; vB.y = acc[mf][nf][3] * scB;
            *(float2*)(opA + px) = vA;
            *(float2*)(opB + px) = vB;
        }
    }
}

// ---------------------------------------------------------------------------
extern "C" void kernel_launch(void* const* d_in, const int* in_sizes, int n_in,
                              void* d_out, int out_size) {
    const float* input = (const float*)d_in[0];
    const float* style = (const float*)d_in[1];
    const float* convw = (const float*)d_in[2];
    const float* modw  = (const float*)d_in[3];
    const float* modb  = (const float*)d_in[4];
    float* out = (float*)d_out;

    static int init_done = 0;
    if (!init_done) {
        cudaFuncSetAttribute(gemm_kernel, cudaFuncAttributeMaxDynamicSharedMemorySize, DYN_SMEM);
        init_done = 1;
    }

    style_kernel<<<B_, STYLE_D>>>(style, modw, modb);
    wsq_kernel<<<(C_OUT * C_IN + 511) / 512, 512>>>(convw);
    demod_kernel<<<B_, C_OUT>>>();
    apack_kernel<<<dim3(18, C_OUT), 256>>>(convw);
    im2col_kernel<<<dim3(16, 64, B_), 256>>>(input);
    gemm_kernel<<<dim3(4, 32, 16), 256, DYN_SMEM>>>(out);
}